// round 14
// baseline (speedup 1.0000x reference)
#include <cuda_runtime.h>
#include <math.h>
#include <stdint.h>

#define NROWS_MAX 65536
#define DD 64
#define dH 32
#define HH 512
#define LL 8
#define KK 10

// ---------------------------------------------------------------------------
// Static device scratch
// ---------------------------------------------------------------------------
__device__ __align__(16) float g_X[2][NROWS_MAX * DD];
__device__ float g_det[NROWS_MAX];
__device__ float g_part[512 * 128];
__device__ __align__(16) float g_mu[DD];
__device__ __align__(16) float g_rstd[DD];

// pre-split bf16 weight buffers (hi / lo)
#define WTOT 4718592
#define OFF_SW0 0
#define OFF_TW0 131072
#define OFF_SW1 262144
#define OFF_TW1 2359296
#define OFF_SW2 4456448
#define OFF_TW2 4587520
__device__ __align__(16) unsigned short g_Wh[WTOT];
__device__ __align__(16) unsigned short g_Wl[WTOT];
__device__ __align__(16) unsigned short g_H0h[2 * NROWS_MAX * HH];
__device__ __align__(16) unsigned short g_H0l[2 * NROWS_MAX * HH];
__device__ __align__(16) unsigned short g_H1h[2 * NROWS_MAX * HH];
__device__ __align__(16) unsigned short g_H1l[2 * NROWS_MAX * HH];

// ---------------------------------------------------------------------------
// portable PTX helpers
// ---------------------------------------------------------------------------
__device__ __forceinline__ uint32_t smem_u32(const void* p) {
    uint32_t a;
    asm("{ .reg .u64 t; cvta.to.shared.u64 t, %1; cvt.u32.u64 %0, t; }"
        : "=r"(a) : "l"(p));
    return a;
}
__device__ __forceinline__ void mma_bf16(float* c, const uint32_t* a,
                                         const uint32_t* b) {
    asm volatile(
        "mma.sync.aligned.m16n8k16.row.col.f32.bf16.bf16.f32 "
        "{%0,%1,%2,%3}, {%4,%5,%6,%7}, {%8,%9}, {%0,%1,%2,%3};"
        : "+f"(c[0]), "+f"(c[1]), "+f"(c[2]), "+f"(c[3])
        : "r"(a[0]), "r"(a[1]), "r"(a[2]), "r"(a[3]), "r"(b[0]), "r"(b[1]));
}
__device__ __forceinline__ void ldsm4(uint32_t* r, uint32_t addr) {
    asm volatile(
        "ldmatrix.sync.aligned.m8n8.x4.shared.b16 {%0,%1,%2,%3}, [%4];"
        : "=r"(r[0]), "=r"(r[1]), "=r"(r[2]), "=r"(r[3]) : "r"(addr));
}
__device__ __forceinline__ void ldsm2(uint32_t* r, uint32_t addr) {
    asm volatile(
        "ldmatrix.sync.aligned.m8n8.x2.shared.b16 {%0,%1}, [%2];"
        : "=r"(r[0]), "=r"(r[1]) : "r"(addr));
}
__device__ __forceinline__ uint32_t packbf(float v1, float v0) {
    uint32_t r;
    asm("cvt.rn.bf16x2.f32 %0, %1, %2;" : "=r"(r) : "f"(v1), "f"(v0));
    return r;
}
__device__ __forceinline__ void spl2(float v0, float v1, uint32_t& h,
                                     uint32_t& l) {
    h = packbf(v1, v0);
    float h0 = __uint_as_float(h << 16);
    float h1 = __uint_as_float(h & 0xffff0000u);
    l = packbf(v1 - h1, v0 - h0);
}
#define CP16(dst, src)                                                        \
    asm volatile("cp.async.ca.shared.global [%0], [%1], 16;" ::"r"(           \
                     (uint32_t)(dst)),                                        \
                 "l"(src))
#define CP_COMMIT() asm volatile("cp.async.commit_group;" ::: "memory")
#define CP_WAITG1() asm volatile("cp.async.wait_group 1;" ::: "memory")
#define CP_WAIT0() asm volatile("cp.async.wait_group 0;" ::: "memory")

// ---------------------------------------------------------------------------
// small kernels
// ---------------------------------------------------------------------------
__global__ void copy_in_kernel(const float* __restrict__ x,
                               float* __restrict__ X, int N) {
    int idx = blockIdx.x * 256 + threadIdx.x;
    if (idx < N * DD) {
        int i = idx >> 6;
        int j = idx & 63;
        X[idx] = x[(size_t)i * (DD + 1) + j];
    }
}

__global__ void wsplit_kernel(const float* __restrict__ src,
                              unsigned short* __restrict__ dh,
                              unsigned short* __restrict__ dl, int n2) {
    int i = blockIdx.x * 256 + threadIdx.x;
    if (i < n2) {
        float2 v = ((const float2*)src)[i];
        uint32_t h, l;
        spl2(v.x, v.y, h, l);
        ((uint32_t*)dh)[i] = h;
        ((uint32_t*)dl)[i] = l;
    }
}

__global__ __launch_bounds__(256) void stats1_kernel(
    const float* __restrict__ X, float* __restrict__ part, int rowsPerBlock) {
    int tid = threadIdx.x;
    int c = tid & 63;
    int rg = tid >> 6;
    size_t base = (size_t)blockIdx.x * rowsPerBlock;
    float s = 0.f, q = 0.f;
    for (int r = rg; r < rowsPerBlock; r += 4) {
        float v = X[(base + r) * DD + c];
        s += v;
        q += v * v;
    }
    __shared__ float ss[256], sq[256];
    ss[tid] = s;
    sq[tid] = q;
    __syncthreads();
    if (tid < 64) {
        float S = ss[tid] + ss[tid + 64] + ss[tid + 128] + ss[tid + 192];
        float Q = sq[tid] + sq[tid + 64] + sq[tid + 128] + sq[tid + 192];
        part[blockIdx.x * 128 + tid] = S;
        part[blockIdx.x * 128 + 64 + tid] = Q;
    }
}

__global__ void stats2_kernel(const float* __restrict__ part, int nb,
                              float invN, float* __restrict__ muArr,
                              float* __restrict__ rstdArr) {
    int c = threadIdx.x;
    float s = 0.f, q = 0.f;
    for (int b = 0; b < nb; b++) {
        s += part[b * 128 + c];
        q += part[b * 128 + 64 + c];
    }
    float m = s * invN;
    float var = q * invN - m * m;
    muArr[c] = m;
    rstdArr[c] = rsqrtf(var + 1e-5f);
}

// ---------------------------------------------------------------------------
// Tile layout: pitch 64 B (32 k bf16), chunk-swizzled: chunk' = chunk^(row&3).
// 8-row ldmatrix phases have a 2-way conflict (rows r/r+4) - measured
// non-binding (R10/R12 insensitivity). Tile = 8192 B.
// ---------------------------------------------------------------------------
#define TILS 8192
#define STG2 (4 * TILS)       // GEMM2 stage: Ah, Al, Wh, Wl = 32768 B
#define SMEM_G2 (3 * STG2)    // 98304 B -> 2 CTAs/SM
#define BTS 2048
#define STG3 (4 * TILS + 4 * BTS)  // 40960 B
#define SMEM_3 (3 * STG3)          // 122880 B
#define SMEM_G1 (4 * TILS)         // 32768 B single stage

// ---------------------------------------------------------------------------
// GEMM1 (K=32, single stage) with fused batchnorm on the A load.
// A = (X[:, x1off:x1off+32] - mu) * rstd, split to bf16 hi/lo in-kernel.
// C(hi,lo) = split(relu(A @ W^T + b)). blockIdx.z = s/t.
// ---------------------------------------------------------------------------
__global__ __launch_bounds__(256, 2) void gemm1_kernel(
    const float* __restrict__ X, int x1off,
    const unsigned short* __restrict__ Wh0,
    const unsigned short* __restrict__ Wl0,
    const unsigned short* __restrict__ Wh1,
    const unsigned short* __restrict__ Wl1, const float* __restrict__ b0,
    const float* __restrict__ b1, unsigned short* __restrict__ Ch0,
    unsigned short* __restrict__ Cl0, unsigned short* __restrict__ Ch1,
    unsigned short* __restrict__ Cl1, const float* __restrict__ mu,
    const float* __restrict__ rstd) {
    extern __shared__ uint32_t smu[];
    char* smc = (char*)smu;
    const int z = blockIdx.z;
    const unsigned short* Wh = z ? Wh1 : Wh0;
    const unsigned short* Wl = z ? Wl1 : Wl0;
    const float* bias = z ? b1 : b0;
    unsigned short* Ch = z ? Ch1 : Ch0;
    unsigned short* Cl = z ? Cl1 : Cl0;

    const int tid = threadIdx.x;
    const int wid = tid >> 5, lane = tid & 31;
    const int wm = wid & 1, wn = wid >> 1;
    const size_t row0 = (size_t)blockIdx.y * 128;
    const int col0 = blockIdx.x * 128;
    const uint32_t smb = smem_u32(smu);

    // fill: row = tid>>1, half h = tid&1 -> chunks 2h, 2h+1 (swizzled)
    {
        int row = tid >> 1, h = tid & 1;
        uint32_t c0 = (uint32_t)(((2 * h) ^ (row & 3)) * 16);
        uint32_t c1 = (uint32_t)(((2 * h + 1) ^ (row & 3)) * 16);
        uint32_t d = row * 64;
        // W tiles via cp.async
        const unsigned short* wsrc = Wh + (size_t)(col0 + row) * dH + h * 16;
        CP16(smb + 2 * TILS + d + c0, wsrc);
        CP16(smb + 2 * TILS + d + c1, wsrc + 8);
        wsrc = Wl + (size_t)(col0 + row) * dH + h * 16;
        CP16(smb + 3 * TILS + d + c0, wsrc);
        CP16(smb + 3 * TILS + d + c1, wsrc + 8);
        CP_COMMIT();
        // A: fp32 load + normalize + split + STS
        const float* xr = X + (row0 + row) * DD + x1off + h * 16;
        const float* mp = mu + x1off + h * 16;
        const float* sp = rstd + x1off + h * 16;
        uint32_t hi[8], lo[8];
#pragma unroll
        for (int q = 0; q < 4; ++q) {
            float4 v = *(const float4*)(xr + q * 4);
            float4 m = *(const float4*)(mp + q * 4);
            float4 s = *(const float4*)(sp + q * 4);
            v.x = (v.x - m.x) * s.x;
            v.y = (v.y - m.y) * s.y;
            v.z = (v.z - m.z) * s.z;
            v.w = (v.w - m.w) * s.w;
            spl2(v.x, v.y, hi[q * 2], lo[q * 2]);
            spl2(v.z, v.w, hi[q * 2 + 1], lo[q * 2 + 1]);
        }
        *(uint4*)(smc + d + c0) = *(uint4*)(hi);
        *(uint4*)(smc + d + c1) = *(uint4*)(hi + 4);
        *(uint4*)(smc + TILS + d + c0) = *(uint4*)(lo);
        *(uint4*)(smc + TILS + d + c1) = *(uint4*)(lo + 4);
    }
    CP_WAIT0();
    __syncthreads();

    const int rowSel = (lane & 7) | (((lane >> 3) & 1) << 3);
    const int lrb = lane & 15;
    const uint32_t aoffr = (uint32_t)((wm * 64 + rowSel) * 64);
    const uint32_t cA[2] = {
        (uint32_t)((((lane >> 4)) ^ (lane & 3)) * 16),
        (uint32_t)(((2 + (lane >> 4)) ^ (lane & 3)) * 16)};
    const uint32_t boffr = (uint32_t)((wn * 32 + (lrb & 7)) * 64);
    const uint32_t cB[2] = {(uint32_t)((((lrb >> 3)) ^ (lrb & 3)) * 16),
                            (uint32_t)(((2 + (lrb >> 3)) ^ (lrb & 3)) * 16)};

    float acc[4][4][4];
#pragma unroll
    for (int mt = 0; mt < 4; mt++)
#pragma unroll
        for (int nt = 0; nt < 4; nt++)
#pragma unroll
            for (int e = 0; e < 4; e++) acc[mt][nt][e] = 0.f;

#pragma unroll
    for (int kh = 0; kh < 2; ++kh) {
        uint32_t ah[4][4], al[4][4];
#pragma unroll
        for (int mt = 0; mt < 4; mt++) {
            ldsm4(ah[mt], smb + aoffr + mt * 1024 + cA[kh]);
            ldsm4(al[mt], smb + TILS + aoffr + mt * 1024 + cA[kh]);
        }
#pragma unroll
        for (int nt = 0; nt < 4; nt++) {
            uint32_t bh[2], bl[2];
            ldsm2(bh, smb + 2 * TILS + boffr + nt * 512 + cB[kh]);
            ldsm2(bl, smb + 3 * TILS + boffr + nt * 512 + cB[kh]);
#pragma unroll
            for (int mt = 0; mt < 4; mt++) {
                mma_bf16(acc[mt][nt], ah[mt], bh);
                mma_bf16(acc[mt][nt], ah[mt], bl);
                mma_bf16(acc[mt][nt], al[mt], bh);
            }
        }
    }

    // epilogue: bias + relu + split -> u32 stores
    float bv[4][2];
#pragma unroll
    for (int nt = 0; nt < 4; nt++) {
        int c = col0 + wn * 32 + nt * 8 + ((lane & 3) << 1);
        bv[nt][0] = __ldg(bias + c);
        bv[nt][1] = __ldg(bias + c + 1);
    }
    uint32_t* Chu = (uint32_t*)Ch;
    uint32_t* Clu = (uint32_t*)Cl;
#pragma unroll
    for (int mt = 0; mt < 4; mt++) {
        size_t r0 = row0 + wm * 64 + mt * 16 + (lane >> 2);
#pragma unroll
        for (int nt = 0; nt < 4; nt++) {
            int cc = col0 + wn * 32 + nt * 8 + ((lane & 3) << 1);
            float v0 = fmaxf(acc[mt][nt][0] + bv[nt][0], 0.f);
            float v1 = fmaxf(acc[mt][nt][1] + bv[nt][1], 0.f);
            uint32_t h, l;
            spl2(v0, v1, h, l);
            size_t u = (r0 * HH + cc) >> 1;
            Chu[u] = h;
            Clu[u] = l;
            v0 = fmaxf(acc[mt][nt][2] + bv[nt][0], 0.f);
            v1 = fmaxf(acc[mt][nt][3] + bv[nt][1], 0.f);
            spl2(v0, v1, h, l);
            u = ((r0 + 8) * HH + cc) >> 1;
            Chu[u] = h;
            Clu[u] = l;
        }
    }
}

// ---------------------------------------------------------------------------
// GEMM2 (K=512): 3-stage cp.async pipeline (prefetch distance 2), 2 CTAs/SM.
// ---------------------------------------------------------------------------
__global__ __launch_bounds__(256, 2) void gemm2_kernel(
    const unsigned short* __restrict__ Ah0,
    const unsigned short* __restrict__ Al0,
    const unsigned short* __restrict__ Ah1,
    const unsigned short* __restrict__ Al1,
    const unsigned short* __restrict__ Wh0,
    const unsigned short* __restrict__ Wl0,
    const unsigned short* __restrict__ Wh1,
    const unsigned short* __restrict__ Wl1, const float* __restrict__ b0,
    const float* __restrict__ b1, unsigned short* __restrict__ Ch0,
    unsigned short* __restrict__ Cl0, unsigned short* __restrict__ Ch1,
    unsigned short* __restrict__ Cl1) {
    extern __shared__ uint32_t smu[];
    const int z = blockIdx.z;
    const unsigned short* Ah = z ? Ah1 : Ah0;
    const unsigned short* Al = z ? Al1 : Al0;
    const unsigned short* Wh = z ? Wh1 : Wh0;
    const unsigned short* Wl = z ? Wl1 : Wl0;
    const float* bias = z ? b1 : b0;
    unsigned short* Ch = z ? Ch1 : Ch0;
    unsigned short* Cl = z ? Cl1 : Cl0;

    const int tid = threadIdx.x;
    const int wid = tid >> 5, lane = tid & 31;
    const int wm = wid & 1, wn = wid >> 1;
    const size_t row0 = (size_t)blockIdx.y * 128;
    const int col0 = blockIdx.x * 128;
    const uint32_t smb = smem_u32(smu);

    const int NCH = 16;

    const int rowSel = (lane & 7) | (((lane >> 3) & 1) << 3);
    const int lrb = lane & 15;
    const uint32_t aoffr = (uint32_t)((wm * 64 + rowSel) * 64);
    const uint32_t cA[2] = {
        (uint32_t)((((lane >> 4)) ^ (lane & 3)) * 16),
        (uint32_t)(((2 + (lane >> 4)) ^ (lane & 3)) * 16)};
    const uint32_t boffr = (uint32_t)((wn * 32 + (lrb & 7)) * 64);
    const uint32_t cB[2] = {(uint32_t)((((lrb >> 3)) ^ (lrb & 3)) * 16),
                            (uint32_t)(((2 + (lrb >> 3)) ^ (lrb & 3)) * 16)};

    auto issue = [&](int i) {
        const uint32_t base = smb + (i % 3) * STG2;
        const int k0 = i * 32;
#pragma unroll
        for (int q = 0; q < 2; ++q) {
            int slot = tid + q * 256;
            int row = slot >> 2;
            int quarter = slot & 3;
            uint32_t d = row * 64 + ((quarter ^ (row & 3)) * 16);
            size_t asrc = (row0 + row) * (size_t)HH + k0 + quarter * 8;
            size_t bsrc = (size_t)(col0 + row) * HH + k0 + quarter * 8;
            CP16(base + d, Ah + asrc);
            CP16(base + TILS + d, Al + asrc);
            CP16(base + 2 * TILS + d, Wh + bsrc);
            CP16(base + 3 * TILS + d, Wl + bsrc);
        }
        CP_COMMIT();
    };

    float acc[4][4][4];
#pragma unroll
    for (int mt = 0; mt < 4; mt++)
#pragma unroll
        for (int nt = 0; nt < 4; nt++)
#pragma unroll
            for (int e = 0; e < 4; e++) acc[mt][nt][e] = 0.f;

    issue(0);
    issue(1);

    for (int i = 0; i < NCH; ++i) {
        if (i == NCH - 1) { CP_WAIT0(); } else { CP_WAITG1(); }
        __syncthreads();
        if (i + 2 < NCH) issue(i + 2);
        const uint32_t AhB = smb + (i % 3) * STG2;
        const uint32_t AlB = AhB + TILS;
        const uint32_t BhB = AhB + 2 * TILS;
        const uint32_t BlB = AhB + 3 * TILS;
#pragma unroll
        for (int kh = 0; kh < 2; ++kh) {
            uint32_t ah[4][4], al[4][4];
#pragma unroll
            for (int mt = 0; mt < 4; mt++) {
                ldsm4(ah[mt], AhB + aoffr + mt * 1024 + cA[kh]);
                ldsm4(al[mt], AlB + aoffr + mt * 1024 + cA[kh]);
            }
#pragma unroll
            for (int nt = 0; nt < 4; nt++) {
                uint32_t bh[2], bl[2];
                ldsm2(bh, BhB + boffr + nt * 512 + cB[kh]);
                ldsm2(bl, BlB + boffr + nt * 512 + cB[kh]);
#pragma unroll
                for (int mt = 0; mt < 4; mt++) {
                    mma_bf16(acc[mt][nt], ah[mt], bh);
                    mma_bf16(acc[mt][nt], ah[mt], bl);
                    mma_bf16(acc[mt][nt], al[mt], bh);
                }
            }
        }
    }

    float bv[4][2];
#pragma unroll
    for (int nt = 0; nt < 4; nt++) {
        int c = col0 + wn * 32 + nt * 8 + ((lane & 3) << 1);
        bv[nt][0] = __ldg(bias + c);
        bv[nt][1] = __ldg(bias + c + 1);
    }
    uint32_t* Chu = (uint32_t*)Ch;
    uint32_t* Clu = (uint32_t*)Cl;
#pragma unroll
    for (int mt = 0; mt < 4; mt++) {
        size_t r0 = row0 + wm * 64 + mt * 16 + (lane >> 2);
#pragma unroll
        for (int nt = 0; nt < 4; nt++) {
            int cc = col0 + wn * 32 + nt * 8 + ((lane & 3) << 1);
            float v0 = fmaxf(acc[mt][nt][0] + bv[nt][0], 0.f);
            float v1 = fmaxf(acc[mt][nt][1] + bv[nt][1], 0.f);
            uint32_t h, l;
            spl2(v0, v1, h, l);
            size_t u = (r0 * HH + cc) >> 1;
            Chu[u] = h;
            Clu[u] = l;
            v0 = fmaxf(acc[mt][nt][2] + bv[nt][0], 0.f);
            v1 = fmaxf(acc[mt][nt][3] + bv[nt][1], 0.f);
            spl2(v0, v1, h, l);
            u = ((r0 + 8) * HH + cc) >> 1;
            Chu[u] = h;
            Clu[u] = l;
        }
    }
}

// ---------------------------------------------------------------------------
// GEMM3 + fused coupling + fused next-layer batchnorm partials.
// 3-stage pipeline, swizzled pitch-64 tiles.
// ---------------------------------------------------------------------------
__global__ __launch_bounds__(256, 1) void mma_gemm3_kernel(
    const unsigned short* __restrict__ H1sh,
    const unsigned short* __restrict__ H1sl,
    const unsigned short* __restrict__ H1th,
    const unsigned short* __restrict__ H1tl,
    const unsigned short* __restrict__ W2sh,
    const unsigned short* __restrict__ W2sl,
    const unsigned short* __restrict__ W2th,
    const unsigned short* __restrict__ W2tl, const float* __restrict__ b2s,
    const float* __restrict__ b2t, const float* __restrict__ X,
    float* __restrict__ Xn, const float* __restrict__ mu,
    const float* __restrict__ rstd, float* __restrict__ det,
    float* __restrict__ part, int x1off, int first) {
    extern __shared__ uint32_t smu[];
    const int tid = threadIdx.x;
    const int wid = tid >> 5, lane = tid & 31;
    const int wm = wid & 3, wn = wid >> 2;
    const size_t row0 = (size_t)blockIdx.x * 128;
    const uint32_t smb = smem_u32(smu);

    const int rowSel = (lane & 7) | (((lane >> 3) & 1) << 3);
    const int lrb = lane & 15;
    const uint32_t aoffr = (uint32_t)((wm * 32 + rowSel) * 64);
    const uint32_t cA[2] = {
        (uint32_t)((((lane >> 4)) ^ (lane & 3)) * 16),
        (uint32_t)(((2 + (lane >> 4)) ^ (lane & 3)) * 16)};
    const uint32_t boffr = (uint32_t)(((lrb & 7)) * 64);
    const uint32_t cB[2] = {(uint32_t)((((lrb >> 3)) ^ (lrb & 3)) * 16),
                            (uint32_t)(((2 + (lrb >> 3)) ^ (lrb & 3)) * 16)};

    auto issue = [&](int i) {
        const uint32_t base = smb + (i % 3) * STG3;
        const int k0 = i * 32;
#pragma unroll
        for (int q = 0; q < 2; ++q) {
            int slot = tid + q * 256;
            int row = slot >> 2;
            int quarter = slot & 3;
            uint32_t d = row * 64 + ((quarter ^ (row & 3)) * 16);
            size_t asrc = (row0 + row) * (size_t)HH + k0 + quarter * 8;
            CP16(base + d, H1sh + asrc);
            CP16(base + TILS + d, H1sl + asrc);
            CP16(base + 2 * TILS + d, H1th + asrc);
            CP16(base + 3 * TILS + d, H1tl + asrc);
        }
#pragma unroll
        for (int q = 0; q < 2; ++q) {
            int j = tid + q * 256;
            int tile = j >> 7;
            int within = j & 127;
            int row = within >> 2;
            int quarter = within & 3;
            const unsigned short* bs = (tile == 0)   ? W2sh
                                       : (tile == 1) ? W2sl
                                       : (tile == 2) ? W2th
                                                     : W2tl;
            uint32_t d = row * 64 + ((quarter ^ (row & 3)) * 16);
            CP16(base + 4 * TILS + tile * BTS + d,
                 bs + (size_t)row * HH + k0 + quarter * 8);
        }
        CP_COMMIT();
    };

    float acc[2][4][4];
#pragma unroll
    for (int mt = 0; mt < 2; mt++)
#pragma unroll
        for (int nt = 0; nt < 4; nt++)
#pragma unroll
            for (int e = 0; e < 4; e++) acc[mt][nt][e] = 0.f;

    issue(0);
    issue(1);

    for (int i = 0; i < 16; ++i) {
        if (i == 15) { CP_WAIT0(); } else { CP_WAITG1(); }
        __syncthreads();
        if (i + 2 < 16) issue(i + 2);
        const uint32_t base = smb + (i % 3) * STG3;
        const uint32_t AHB = base + (wn ? 2 * TILS : 0);
        const uint32_t ALB = AHB + TILS;
        const uint32_t BHB = base + 4 * TILS + (wn ? 2 * BTS : 0);
        const uint32_t BLB = BHB + BTS;
#pragma unroll
        for (int kh = 0; kh < 2; ++kh) {
            uint32_t ah[2][4], al[2][4];
#pragma unroll
            for (int mt = 0; mt < 2; mt++) {
                ldsm4(ah[mt], AHB + aoffr + mt * 1024 + cA[kh]);
                ldsm4(al[mt], ALB + aoffr + mt * 1024 + cA[kh]);
            }
#pragma unroll
            for (int nt = 0; nt < 4; nt++) {
                uint32_t bh[2], bl[2];
                ldsm2(bh, BHB + boffr + nt * 512 + cB[kh]);
                ldsm2(bl, BLB + boffr + nt * 512 + cB[kh]);
#pragma unroll
                for (int mt = 0; mt < 2; mt++) {
                    mma_bf16(acc[mt][nt], ah[mt], bh);
                    mma_bf16(acc[mt][nt], ah[mt], bl);
                    mma_bf16(acc[mt][nt], al[mt], bh);
                }
            }
        }
    }
    __syncthreads();

    float* Cs = (float*)smu;  // [128][66]
    {
        const float* bp = wn ? b2t : b2s;
#pragma unroll
        for (int mt = 0; mt < 2; mt++) {
            int r = wm * 32 + mt * 16 + (lane >> 2);
#pragma unroll
            for (int nt = 0; nt < 4; nt++) {
                int ccl = nt * 8 + ((lane & 3) << 1);
                int cg = wn * 32 + ccl;
                float bv0 = __ldg(bp + ccl), bv1 = __ldg(bp + ccl + 1);
                Cs[r * 66 + cg] = acc[mt][nt][0] + bv0;
                Cs[r * 66 + cg + 1] = acc[mt][nt][1] + bv1;
                Cs[(r + 8) * 66 + cg] = acc[mt][nt][2] + bv0;
                Cs[(r + 8) * 66 + cg + 1] = acc[mt][nt][3] + bv1;
            }
        }
    }
    __syncthreads();

    if (tid < 128) {
        int r = tid;
        size_t grow = row0 + r;
        const float* xr = X + grow * DD;
        float* xo = Xn + grow * DD;
        int x2off = dH - x1off;
        float ssum = 0.f;
#pragma unroll 8
        for (int j = 0; j < dH; j++) {
            float s = Cs[r * 66 + j];
            float t = Cs[r * 66 + 32 + j];
            float x1 = xr[x1off + j];
            float x2 = xr[x2off + j];
            float x1n = (x1 - mu[x1off + j]) * rstd[x1off + j];
            float x2n = (x2 - mu[x2off + j]) * rstd[x2off + j];
            float y2 = x2n * expf(s) + t;
            xo[j] = x1n;
            xo[dH + j] = y2;
            Cs[r * 66 + j] = x1n;
            Cs[r * 66 + 32 + j] = y2;
            ssum += s;
        }
        det[grow] = first ? ssum : (det[grow] + ssum);
    }
    __syncthreads();

    float* red = (float*)smu + 128 * 66;
    if (tid < 128) {
        int c = tid & 63;
        int half = tid >> 6;
        float s = 0.f, q = 0.f;
        int rbeg = half * 64;
#pragma unroll 4
        for (int r = rbeg; r < rbeg + 64; ++r) {
            float v = Cs[r * 66 + c];
            s += v;
            q += v * v;
        }
        red[tid] = s;
        red[128 + tid] = q;
    }
    __syncthreads();
    if (tid < 64) {
        part[blockIdx.x * 128 + tid] = red[tid] + red[64 + tid];
        part[blockIdx.x * 128 + 64 + tid] =
            red[128 + tid] + red[128 + 64 + tid];
    }
}

// ---------------------------------------------------------------------------
// GMM log-likelihood + output assembly + final reduce (unchanged, proven)
// ---------------------------------------------------------------------------
__global__ __launch_bounds__(256) void gmm_kernel(
    const float* __restrict__ X, const float* __restrict__ means,
    const float* __restrict__ det, float* __restrict__ out, int N, int full) {
    __shared__ float smm[KK * DD];
    int tid = threadIdx.x;
    for (int i = tid; i < KK * DD; i += 256) smm[i] = means[i];
    __syncthreads();

    size_t i = (size_t)blockIdx.x * 256 + tid;
    float4 y4[16];
    const float4* xr = (const float4*)(X + i * DD);
#pragma unroll
    for (int q = 0; q < 16; q++) y4[q] = xr[q];
    float4* yo = (float4*)(out + i * DD);
#pragma unroll
    for (int q = 0; q < 16; q++) yo[q] = y4[q];

    if (!full) return;

    const float CD = (float)(64.0 * 1.8378770664093453);
    float lp[KK];
    float mx = -1e30f;
#pragma unroll
    for (int k = 0; k < KK; k++) {
        const float* mrow = smm + k * DD;
        float accv = 0.f;
#pragma unroll
        for (int q = 0; q < 16; q++) {
            float4 m4 = *(const float4*)(mrow + q * 4);
            float dx = y4[q].x - m4.x;
            accv += dx * dx;
            dx = y4[q].y - m4.y;
            accv += dx * dx;
            dx = y4[q].z - m4.z;
            accv += dx * dx;
            dx = y4[q].w - m4.w;
            accv += dx * dx;
        }
        float v = -0.5f * (accv + CD);
        lp[k] = v;
        mx = fmaxf(mx, v);
    }
    float se = 0.f;
#pragma unroll
    for (int k = 0; k < KK; k++) se += expf(lp[k] - mx);
    float ll = mx + logf(se) - logf((float)KK);

    size_t oll = (size_t)N * DD + 1;
    out[oll + i] = ll;
    out[oll + N + i] = det[i];
}

__global__ void final_reduce_kernel(float* __restrict__ out, int N) {
    int tid = threadIdx.x;
    size_t oll = (size_t)N * DD + 1;
    size_t odet = oll + N;
    float sll = 0.f, sdet = 0.f;
    for (int i = tid; i < N; i += 1024) {
        sll += out[oll + i];
        sdet += out[odet + i];
    }
    __shared__ float a[1024], b[1024];
    a[tid] = sll;
    b[tid] = sdet;
    __syncthreads();
    for (int s = 512; s > 0; s >>= 1) {
        if (tid < s) {
            a[tid] += a[tid + s];
            b[tid] += b[tid + s];
        }
        __syncthreads();
    }
    if (tid == 0) {
        float llm = a[0] / (float)N;
        float dm = b[0] / (float)N;
        out[(size_t)N * DD] = -(dm + llm);
        out[odet + N] = llm;
        out[odet + N + 1] = dm;
    }
}

// ---------------------------------------------------------------------------
// Host launcher
// ---------------------------------------------------------------------------
static void* symaddr_v(const void* s) {
    void* p = nullptr;
    cudaGetSymbolAddress(&p, s);
    return p;
}

extern "C" void kernel_launch(void* const* d_in, const int* in_sizes, int n_in,
                              void* d_out, int out_size) {
    const float* x = (const float*)d_in[0];
    const float* sW0 = (const float*)d_in[1];
    const float* sb0 = (const float*)d_in[2];
    const float* sW1 = (const float*)d_in[3];
    const float* sb1 = (const float*)d_in[4];
    const float* sW2 = (const float*)d_in[5];
    const float* sb2 = (const float*)d_in[6];
    const float* tW0 = (const float*)d_in[7];
    const float* tb0 = (const float*)d_in[8];
    const float* tW1 = (const float*)d_in[9];
    const float* tb1 = (const float*)d_in[10];
    const float* tW2 = (const float*)d_in[11];
    const float* tb2 = (const float*)d_in[12];
    const float* means = (const float*)d_in[13];
    float* out = (float*)d_out;

    const int N = in_sizes[0] / (DD + 1);
    const int full = (out_size >= (long long)N * DD + 2 * N + 3) ? 1 : 0;

    cudaFuncSetAttribute(gemm2_kernel,
                         cudaFuncAttributeMaxDynamicSharedMemorySize, SMEM_G2);
    cudaFuncSetAttribute(mma_gemm3_kernel,
                         cudaFuncAttributeMaxDynamicSharedMemorySize, SMEM_3);

    float* X = (float*)symaddr_v(g_X);
    float* det = (float*)symaddr_v(g_det);
    float* part = (float*)symaddr_v(g_part);
    float* mu = (float*)symaddr_v(g_mu);
    float* rstd = (float*)symaddr_v(g_rstd);
    unsigned short* Wh = (unsigned short*)symaddr_v(g_Wh);
    unsigned short* Wl = (unsigned short*)symaddr_v(g_Wl);
    unsigned short* H0h = (unsigned short*)symaddr_v(g_H0h);
    unsigned short* H0l = (unsigned short*)symaddr_v(g_H0l);
    unsigned short* H1h = (unsigned short*)symaddr_v(g_H1h);
    unsigned short* H1l = (unsigned short*)symaddr_v(g_H1l);

    const size_t XS = (size_t)N * DD;
    const size_t HS = (size_t)N * HH;

    copy_in_kernel<<<(N * DD + 255) / 256, 256>>>(x, X, N);

    wsplit_kernel<<<(65536 + 255) / 256, 256>>>(sW0, Wh + OFF_SW0,
                                                Wl + OFF_SW0, 65536);
    wsplit_kernel<<<(65536 + 255) / 256, 256>>>(tW0, Wh + OFF_TW0,
                                                Wl + OFF_TW0, 65536);
    wsplit_kernel<<<(1048576 + 255) / 256, 256>>>(sW1, Wh + OFF_SW1,
                                                  Wl + OFF_SW1, 1048576);
    wsplit_kernel<<<(1048576 + 255) / 256, 256>>>(tW1, Wh + OFF_TW1,
                                                  Wl + OFF_TW1, 1048576);
    wsplit_kernel<<<(65536 + 255) / 256, 256>>>(sW2, Wh + OFF_SW2,
                                                Wl + OFF_SW2, 65536);
    wsplit_kernel<<<(65536 + 255) / 256, 256>>>(tW2, Wh + OFF_TW2,
                                                Wl + OFF_TW2, 65536);

    int cur = 0;
    for (int l = 0; l < LL; l++) {
        float* Xc = X + (size_t)cur * XS;
        float* Xnext = X + (size_t)(cur ^ 1) * XS;

        if (l == 0) {
            stats1_kernel<<<256, 256>>>(Xc, part, N / 256);
            stats2_kernel<<<1, 64>>>(part, 256, 1.0f / (float)N, mu, rstd);
        } else {
            stats2_kernel<<<1, 64>>>(part, N / 128, 1.0f / (float)N, mu, rstd);
        }

        const int x1off = (l & 1) ? dH : 0;

        // GEMM1 with fused batchnorm-normalize on A
        gemm1_kernel<<<dim3(HH / 128, N / 128, 2), 256, SMEM_G1>>>(
            Xc, x1off,
            Wh + OFF_SW0 + (size_t)l * HH * dH, Wl + OFF_SW0 + (size_t)l * HH * dH,
            Wh + OFF_TW0 + (size_t)l * HH * dH, Wl + OFF_TW0 + (size_t)l * HH * dH,
            sb0 + (size_t)l * HH, tb0 + (size_t)l * HH,
            H0h, H0l, H0h + HS, H0l + HS, mu, rstd);

        gemm2_kernel<<<dim3(HH / 128, N / 128, 2), 256, SMEM_G2>>>(
            H0h, H0l, H0h + HS, H0l + HS,
            Wh + OFF_SW1 + (size_t)l * HH * HH, Wl + OFF_SW1 + (size_t)l * HH * HH,
            Wh + OFF_TW1 + (size_t)l * HH * HH, Wl + OFF_TW1 + (size_t)l * HH * HH,
            sb1 + (size_t)l * HH, tb1 + (size_t)l * HH,
            H1h, H1l, H1h + HS, H1l + HS);

        mma_gemm3_kernel<<<N / 128, 256, SMEM_3>>>(
            H1h, H1l, H1h + HS, H1l + HS,
            Wh + OFF_SW2 + (size_t)l * dH * HH, Wl + OFF_SW2 + (size_t)l * dH * HH,
            Wh + OFF_TW2 + (size_t)l * dH * HH, Wl + OFF_TW2 + (size_t)l * dH * HH,
            sb2 + (size_t)l * dH, tb2 + (size_t)l * dH, Xc, Xnext, mu, rstd,
            det, part, x1off, (l == 0) ? 1 : 0);

        cur ^= 1;
    }

    gmm_kernel<<<N / 256, 256>>>(X + (size_t)cur * XS, means, det, out, N,
                                 full);
    if (full) final_reduce_kernel<<<1, 1024>>>(out, N);
}

// round 15
// speedup vs baseline: 1.0788x; 1.0788x over previous
#include <cuda_runtime.h>
#include <math.h>
#include <stdint.h>

#define NROWS_MAX 65536
#define DD 64
#define dH 32
#define HH 512
#define LL 8
#define KK 10

// ---------------------------------------------------------------------------
// Static device scratch
// ---------------------------------------------------------------------------
__device__ __align__(16) float g_X[2][NROWS_MAX * DD];
__device__ float g_det[NROWS_MAX];
__device__ float g_part[512 * 128];
__device__ __align__(16) float g_mu[DD];
__device__ __align__(16) float g_rstd[DD];

// pre-split bf16 weight buffers (hi / lo)
#define WTOT 4718592
#define OFF_SW0 0
#define OFF_TW0 131072
#define OFF_SW1 262144
#define OFF_TW1 2359296
#define OFF_SW2 4456448
#define OFF_TW2 4587520
__device__ __align__(16) unsigned short g_Wh[WTOT];
__device__ __align__(16) unsigned short g_Wl[WTOT];
__device__ __align__(16) unsigned short g_H0h[2 * NROWS_MAX * HH];
__device__ __align__(16) unsigned short g_H0l[2 * NROWS_MAX * HH];
__device__ __align__(16) unsigned short g_H1h[2 * NROWS_MAX * HH];
__device__ __align__(16) unsigned short g_H1l[2 * NROWS_MAX * HH];

// ---------------------------------------------------------------------------
// portable PTX helpers
// ---------------------------------------------------------------------------
__device__ __forceinline__ uint32_t smem_u32(const void* p) {
    uint32_t a;
    asm("{ .reg .u64 t; cvta.to.shared.u64 t, %1; cvt.u32.u64 %0, t; }"
        : "=r"(a) : "l"(p));
    return a;
}
__device__ __forceinline__ void mma_bf16(float* c, const uint32_t* a,
                                         const uint32_t* b) {
    asm volatile(
        "mma.sync.aligned.m16n8k16.row.col.f32.bf16.bf16.f32 "
        "{%0,%1,%2,%3}, {%4,%5,%6,%7}, {%8,%9}, {%0,%1,%2,%3};"
        : "+f"(c[0]), "+f"(c[1]), "+f"(c[2]), "+f"(c[3])
        : "r"(a[0]), "r"(a[1]), "r"(a[2]), "r"(a[3]), "r"(b[0]), "r"(b[1]));
}
__device__ __forceinline__ void ldsm4(uint32_t* r, uint32_t addr) {
    asm volatile(
        "ldmatrix.sync.aligned.m8n8.x4.shared.b16 {%0,%1,%2,%3}, [%4];"
        : "=r"(r[0]), "=r"(r[1]), "=r"(r[2]), "=r"(r[3]) : "r"(addr));
}
__device__ __forceinline__ void ldsm2(uint32_t* r, uint32_t addr) {
    asm volatile(
        "ldmatrix.sync.aligned.m8n8.x2.shared.b16 {%0,%1}, [%2];"
        : "=r"(r[0]), "=r"(r[1]) : "r"(addr));
}
__device__ __forceinline__ uint32_t packbf(float v1, float v0) {
    uint32_t r;
    asm("cvt.rn.bf16x2.f32 %0, %1, %2;" : "=r"(r) : "f"(v1), "f"(v0));
    return r;
}
__device__ __forceinline__ void spl2(float v0, float v1, uint32_t& h,
                                     uint32_t& l) {
    h = packbf(v1, v0);
    float h0 = __uint_as_float(h << 16);
    float h1 = __uint_as_float(h & 0xffff0000u);
    l = packbf(v1 - h1, v0 - h0);
}
#define CP16(dst, src)                                                        \
    asm volatile("cp.async.ca.shared.global [%0], [%1], 16;" ::"r"(           \
                     (uint32_t)(dst)),                                        \
                 "l"(src))
#define CP_COMMIT() asm volatile("cp.async.commit_group;" ::: "memory")
#define CP_WAIT0() asm volatile("cp.async.wait_group 0;" ::: "memory")

// ---------------------------------------------------------------------------
// small kernels
// ---------------------------------------------------------------------------
__global__ void copy_in_kernel(const float* __restrict__ x,
                               float* __restrict__ X, int N) {
    int idx = blockIdx.x * 256 + threadIdx.x;
    if (idx < N * DD) {
        int i = idx >> 6;
        int j = idx & 63;
        X[idx] = x[(size_t)i * (DD + 1) + j];
    }
}

__global__ void wsplit_kernel(const float* __restrict__ src,
                              unsigned short* __restrict__ dh,
                              unsigned short* __restrict__ dl, int n2) {
    int i = blockIdx.x * 256 + threadIdx.x;
    if (i < n2) {
        float2 v = ((const float2*)src)[i];
        uint32_t h, l;
        spl2(v.x, v.y, h, l);
        ((uint32_t*)dh)[i] = h;
        ((uint32_t*)dl)[i] = l;
    }
}

__global__ __launch_bounds__(256) void stats1_kernel(
    const float* __restrict__ X, float* __restrict__ part, int rowsPerBlock) {
    int tid = threadIdx.x;
    int c = tid & 63;
    int rg = tid >> 6;
    size_t base = (size_t)blockIdx.x * rowsPerBlock;
    float s = 0.f, q = 0.f;
    for (int r = rg; r < rowsPerBlock; r += 4) {
        float v = X[(base + r) * DD + c];
        s += v;
        q += v * v;
    }
    __shared__ float ss[256], sq[256];
    ss[tid] = s;
    sq[tid] = q;
    __syncthreads();
    if (tid < 64) {
        float S = ss[tid] + ss[tid + 64] + ss[tid + 128] + ss[tid + 192];
        float Q = sq[tid] + sq[tid + 64] + sq[tid + 128] + sq[tid + 192];
        part[blockIdx.x * 128 + tid] = S;
        part[blockIdx.x * 128 + 64 + tid] = Q;
    }
}

__global__ void stats2_kernel(const float* __restrict__ part, int nb,
                              float invN, float* __restrict__ muArr,
                              float* __restrict__ rstdArr) {
    int c = threadIdx.x;
    float s = 0.f, q = 0.f;
    for (int b = 0; b < nb; b++) {
        s += part[b * 128 + c];
        q += part[b * 128 + 64 + c];
    }
    float m = s * invN;
    float var = q * invN - m * m;
    muArr[c] = m;
    rstdArr[c] = rsqrtf(var + 1e-5f);
}

// ---------------------------------------------------------------------------
// Tile layout (R13-proven): row pitch 80 B (32 k bf16 = 64 B + 16 B pad).
// ---------------------------------------------------------------------------
#define PCHB 80
#define TILB2 (128 * PCHB)     // 10240 B
#define STGB2 (4 * TILB2)      // 40960 B
#define SMEMG2 (2 * STGB2)     // 81920 B
#define BTB2 (32 * PCHB)
#define STG3B2 (4 * TILB2 + 4 * BTB2)
#define SMEM3B (2 * STG3B2)
#define SMEMG1 STGB2           // single stage

// ---------------------------------------------------------------------------
// GEMM1 (K=32, single stage) with FUSED batchnorm on the A load.
// A = (X[:, x1off:+32] - mu) * rstd, split to bf16 hi/lo in-kernel (STS);
// W tiles via cp.async. Pitch-80 tiles identical to R13's layout.
// ---------------------------------------------------------------------------
__global__ __launch_bounds__(256, 2) void gemm1_kernel(
    const float* __restrict__ X, int x1off,
    const unsigned short* __restrict__ Wh0,
    const unsigned short* __restrict__ Wl0,
    const unsigned short* __restrict__ Wh1,
    const unsigned short* __restrict__ Wl1, const float* __restrict__ b0,
    const float* __restrict__ b1, unsigned short* __restrict__ Ch0,
    unsigned short* __restrict__ Cl0, unsigned short* __restrict__ Ch1,
    unsigned short* __restrict__ Cl1, const float* __restrict__ mu,
    const float* __restrict__ rstd) {
    extern __shared__ uint32_t smu[];
    char* smc = (char*)smu;
    const int z = blockIdx.z;
    const unsigned short* Wh = z ? Wh1 : Wh0;
    const unsigned short* Wl = z ? Wl1 : Wl0;
    const float* bias = z ? b1 : b0;
    unsigned short* Ch = z ? Ch1 : Ch0;
    unsigned short* Cl = z ? Cl1 : Cl0;

    const int tid = threadIdx.x;
    const int wid = tid >> 5, lane = tid & 31;
    const int wm = wid & 1, wn = wid >> 1;
    const size_t row0 = (size_t)blockIdx.y * 128;
    const int col0 = blockIdx.x * 128;
    const uint32_t smb = smem_u32(smu);

    // fill: row = tid>>1, half h = tid&1 covers 16 k-elements (32 B)
    {
        int row = tid >> 1, h = tid & 1;
        uint32_t d = row * PCHB + h * 32;
        // W tiles via cp.async (2 x 16B per thread per tile)
        const unsigned short* wsrc = Wh + (size_t)(col0 + row) * dH + h * 16;
        CP16(smb + 2 * TILB2 + d, wsrc);
        CP16(smb + 2 * TILB2 + d + 16, wsrc + 8);
        wsrc = Wl + (size_t)(col0 + row) * dH + h * 16;
        CP16(smb + 3 * TILB2 + d, wsrc);
        CP16(smb + 3 * TILB2 + d + 16, wsrc + 8);
        CP_COMMIT();
        // A: fp32 load + normalize + split + STS
        const float* xr = X + (row0 + row) * DD + x1off + h * 16;
        const float* mp = mu + x1off + h * 16;
        const float* sp = rstd + x1off + h * 16;
        uint32_t hi[8], lo[8];
#pragma unroll
        for (int q = 0; q < 4; ++q) {
            float4 v = *(const float4*)(xr + q * 4);
            float4 m = *(const float4*)(mp + q * 4);
            float4 s = *(const float4*)(sp + q * 4);
            v.x = (v.x - m.x) * s.x;
            v.y = (v.y - m.y) * s.y;
            v.z = (v.z - m.z) * s.z;
            v.w = (v.w - m.w) * s.w;
            spl2(v.x, v.y, hi[q * 2], lo[q * 2]);
            spl2(v.z, v.w, hi[q * 2 + 1], lo[q * 2 + 1]);
        }
        *(uint4*)(smc + d) = *(uint4*)(hi);
        *(uint4*)(smc + d + 16) = *(uint4*)(hi + 4);
        *(uint4*)(smc + TILB2 + d) = *(uint4*)(lo);
        *(uint4*)(smc + TILB2 + d + 16) = *(uint4*)(lo + 4);
    }
    CP_WAIT0();
    __syncthreads();

    const int rowSel = (lane & 7) | (((lane >> 3) & 1) << 3);
    const int kSelA = (lane >> 4) * 16;
    const int lrb = lane & 15;
    const uint32_t aoff = (uint32_t)((wm * 64 + rowSel) * PCHB + kSelA);
    const uint32_t boff =
        (uint32_t)((wn * 32 + (lrb & 7)) * PCHB + (lrb >> 3) * 16);

    float acc[4][4][4];
#pragma unroll
    for (int mt = 0; mt < 4; mt++)
#pragma unroll
        for (int nt = 0; nt < 4; nt++)
#pragma unroll
            for (int e = 0; e < 4; e++) acc[mt][nt][e] = 0.f;

#pragma unroll
    for (int kh = 0; kh < 2; ++kh) {
        uint32_t ah[4][4], al[4][4];
#pragma unroll
        for (int mt = 0; mt < 4; mt++) {
            ldsm4(ah[mt], smb + aoff + mt * 16 * PCHB + kh * 32);
            ldsm4(al[mt], smb + TILB2 + aoff + mt * 16 * PCHB + kh * 32);
        }
#pragma unroll
        for (int nt = 0; nt < 4; nt++) {
            uint32_t bh[2], bl[2];
            ldsm2(bh, smb + 2 * TILB2 + boff + nt * 8 * PCHB + kh * 32);
            ldsm2(bl, smb + 3 * TILB2 + boff + nt * 8 * PCHB + kh * 32);
#pragma unroll
            for (int mt = 0; mt < 4; mt++) {
                mma_bf16(acc[mt][nt], ah[mt], bh);
                mma_bf16(acc[mt][nt], ah[mt], bl);
                mma_bf16(acc[mt][nt], al[mt], bh);
            }
        }
    }

    // epilogue: bias + relu + split -> u32 stores
    float bv[4][2];
#pragma unroll
    for (int nt = 0; nt < 4; nt++) {
        int c = col0 + wn * 32 + nt * 8 + ((lane & 3) << 1);
        bv[nt][0] = __ldg(bias + c);
        bv[nt][1] = __ldg(bias + c + 1);
    }
    uint32_t* Chu = (uint32_t*)Ch;
    uint32_t* Clu = (uint32_t*)Cl;
#pragma unroll
    for (int mt = 0; mt < 4; mt++) {
        size_t r0 = row0 + wm * 64 + mt * 16 + (lane >> 2);
#pragma unroll
        for (int nt = 0; nt < 4; nt++) {
            int cc = col0 + wn * 32 + nt * 8 + ((lane & 3) << 1);
            float v0 = fmaxf(acc[mt][nt][0] + bv[nt][0], 0.f);
            float v1 = fmaxf(acc[mt][nt][1] + bv[nt][1], 0.f);
            uint32_t h, l;
            spl2(v0, v1, h, l);
            size_t u = (r0 * HH + cc) >> 1;
            Chu[u] = h;
            Clu[u] = l;
            v0 = fmaxf(acc[mt][nt][2] + bv[nt][0], 0.f);
            v1 = fmaxf(acc[mt][nt][3] + bv[nt][1], 0.f);
            spl2(v0, v1, h, l);
            u = ((r0 + 8) * HH + cc) >> 1;
            Chu[u] = h;
            Clu[u] = l;
        }
    }
}

// ---------------------------------------------------------------------------
// GEMM2 (K=512): R13-proven BK=32, 2-stage, wait0. 2 CTAs/SM.
// ---------------------------------------------------------------------------
__global__ __launch_bounds__(256, 2) void gemm2_kernel(
    const unsigned short* __restrict__ Ah0,
    const unsigned short* __restrict__ Al0,
    const unsigned short* __restrict__ Ah1,
    const unsigned short* __restrict__ Al1,
    const unsigned short* __restrict__ Wh0,
    const unsigned short* __restrict__ Wl0,
    const unsigned short* __restrict__ Wh1,
    const unsigned short* __restrict__ Wl1, const float* __restrict__ b0,
    const float* __restrict__ b1, unsigned short* __restrict__ Ch0,
    unsigned short* __restrict__ Cl0, unsigned short* __restrict__ Ch1,
    unsigned short* __restrict__ Cl1) {
    extern __shared__ uint32_t smu[];
    const int z = blockIdx.z;
    const unsigned short* Ah = z ? Ah1 : Ah0;
    const unsigned short* Al = z ? Al1 : Al0;
    const unsigned short* Wh = z ? Wh1 : Wh0;
    const unsigned short* Wl = z ? Wl1 : Wl0;
    const float* bias = z ? b1 : b0;
    unsigned short* Ch = z ? Ch1 : Ch0;
    unsigned short* Cl = z ? Cl1 : Cl0;

    const int tid = threadIdx.x;
    const int wid = tid >> 5, lane = tid & 31;
    const int wm = wid & 1, wn = wid >> 1;
    const size_t row0 = (size_t)blockIdx.y * 128;
    const int col0 = blockIdx.x * 128;
    const uint32_t smb = smem_u32(smu);

    const int NCH = 16;

    const int rowSel = (lane & 7) | (((lane >> 3) & 1) << 3);
    const int kSelA = (lane >> 4) * 16;
    const int lrb = lane & 15;
    const uint32_t aoff = (uint32_t)((wm * 64 + rowSel) * PCHB + kSelA);
    const uint32_t boff =
        (uint32_t)((wn * 32 + (lrb & 7)) * PCHB + (lrb >> 3) * 16);

    auto issue = [&](int i) {
        const uint32_t base = smb + (i & 1) * STGB2;
        const int k0 = i * 32;
#pragma unroll
        for (int q = 0; q < 2; ++q) {
            int slot = tid + q * 256;
            int row = slot >> 2;
            int quarter = slot & 3;
            uint32_t d = row * PCHB + quarter * 16;
            size_t asrc = (row0 + row) * (size_t)HH + k0 + quarter * 8;
            size_t bsrc = (size_t)(col0 + row) * HH + k0 + quarter * 8;
            CP16(base + d, Ah + asrc);
            CP16(base + TILB2 + d, Al + asrc);
            CP16(base + 2 * TILB2 + d, Wh + bsrc);
            CP16(base + 3 * TILB2 + d, Wl + bsrc);
        }
        CP_COMMIT();
    };

    float acc[4][4][4];
#pragma unroll
    for (int mt = 0; mt < 4; mt++)
#pragma unroll
        for (int nt = 0; nt < 4; nt++)
#pragma unroll
            for (int e = 0; e < 4; e++) acc[mt][nt][e] = 0.f;

    issue(0);

    for (int i = 0; i < NCH; ++i) {
        CP_WAIT0();
        __syncthreads();
        if (i + 1 < NCH) issue(i + 1);
        const uint32_t AhB = smb + (i & 1) * STGB2;
        const uint32_t AlB = AhB + TILB2;
        const uint32_t BhB = AhB + 2 * TILB2;
        const uint32_t BlB = AhB + 3 * TILB2;
#pragma unroll
        for (int kh = 0; kh < 2; ++kh) {
            uint32_t ah[4][4], al[4][4];
#pragma unroll
            for (int mt = 0; mt < 4; mt++) {
                ldsm4(ah[mt], AhB + aoff + mt * 16 * PCHB + kh * 32);
                ldsm4(al[mt], AlB + aoff + mt * 16 * PCHB + kh * 32);
            }
#pragma unroll
            for (int nt = 0; nt < 4; nt++) {
                uint32_t bh[2], bl[2];
                ldsm2(bh, BhB + boff + nt * 8 * PCHB + kh * 32);
                ldsm2(bl, BlB + boff + nt * 8 * PCHB + kh * 32);
#pragma unroll
                for (int mt = 0; mt < 4; mt++) {
                    mma_bf16(acc[mt][nt], ah[mt], bh);
                    mma_bf16(acc[mt][nt], ah[mt], bl);
                    mma_bf16(acc[mt][nt], al[mt], bh);
                }
            }
        }
    }

    float bv[4][2];
#pragma unroll
    for (int nt = 0; nt < 4; nt++) {
        int c = col0 + wn * 32 + nt * 8 + ((lane & 3) << 1);
        bv[nt][0] = __ldg(bias + c);
        bv[nt][1] = __ldg(bias + c + 1);
    }
    uint32_t* Chu = (uint32_t*)Ch;
    uint32_t* Clu = (uint32_t*)Cl;
#pragma unroll
    for (int mt = 0; mt < 4; mt++) {
        size_t r0 = row0 + wm * 64 + mt * 16 + (lane >> 2);
#pragma unroll
        for (int nt = 0; nt < 4; nt++) {
            int cc = col0 + wn * 32 + nt * 8 + ((lane & 3) << 1);
            float v0 = fmaxf(acc[mt][nt][0] + bv[nt][0], 0.f);
            float v1 = fmaxf(acc[mt][nt][1] + bv[nt][1], 0.f);
            uint32_t h, l;
            spl2(v0, v1, h, l);
            size_t u = (r0 * HH + cc) >> 1;
            Chu[u] = h;
            Clu[u] = l;
            v0 = fmaxf(acc[mt][nt][2] + bv[nt][0], 0.f);
            v1 = fmaxf(acc[mt][nt][3] + bv[nt][1], 0.f);
            spl2(v0, v1, h, l);
            u = ((r0 + 8) * HH + cc) >> 1;
            Chu[u] = h;
            Clu[u] = l;
        }
    }
}

// ---------------------------------------------------------------------------
// GEMM3 + fused coupling + fused next-layer batchnorm partials (R13-proven).
// ---------------------------------------------------------------------------
__global__ __launch_bounds__(256, 1) void mma_gemm3_kernel(
    const unsigned short* __restrict__ H1sh,
    const unsigned short* __restrict__ H1sl,
    const unsigned short* __restrict__ H1th,
    const unsigned short* __restrict__ H1tl,
    const unsigned short* __restrict__ W2sh,
    const unsigned short* __restrict__ W2sl,
    const unsigned short* __restrict__ W2th,
    const unsigned short* __restrict__ W2tl, const float* __restrict__ b2s,
    const float* __restrict__ b2t, const float* __restrict__ X,
    float* __restrict__ Xn, const float* __restrict__ mu,
    const float* __restrict__ rstd, float* __restrict__ det,
    float* __restrict__ part, int x1off, int first) {
    extern __shared__ uint32_t smu[];
    const int tid = threadIdx.x;
    const int wid = tid >> 5, lane = tid & 31;
    const int wm = wid & 3, wn = wid >> 2;
    const size_t row0 = (size_t)blockIdx.x * 128;
    const uint32_t smb = smem_u32(smu);

    const int rowSel = (lane & 7) | (((lane >> 3) & 1) << 3);
    const int kSelA = (lane >> 4) * 16;
    const int lrb = lane & 15;
    const uint32_t aoff = (uint32_t)((wm * 32 + rowSel) * PCHB + kSelA);
    const uint32_t boff = (uint32_t)(((lrb & 7)) * PCHB + (lrb >> 3) * 16);

    auto issue = [&](int i) {
        const uint32_t base = smb + (i & 1) * STG3B2;
        const int k0 = i * 32;
#pragma unroll
        for (int q = 0; q < 2; ++q) {
            int slot = tid + q * 256;
            int row = slot >> 2;
            int quarter = slot & 3;
            uint32_t d = row * PCHB + quarter * 16;
            size_t asrc = (row0 + row) * (size_t)HH + k0 + quarter * 8;
            CP16(base + d, H1sh + asrc);
            CP16(base + TILB2 + d, H1sl + asrc);
            CP16(base + 2 * TILB2 + d, H1th + asrc);
            CP16(base + 3 * TILB2 + d, H1tl + asrc);
        }
#pragma unroll
        for (int q = 0; q < 2; ++q) {
            int j = tid + q * 256;
            int tile = j >> 7;
            int within = j & 127;
            int row = within >> 2;
            int quarter = within & 3;
            const unsigned short* bs = (tile == 0)   ? W2sh
                                       : (tile == 1) ? W2sl
                                       : (tile == 2) ? W2th
                                                     : W2tl;
            CP16(base + 4 * TILB2 + tile * BTB2 + row * PCHB + quarter * 16,
                 bs + (size_t)row * HH + k0 + quarter * 8);
        }
        CP_COMMIT();
    };

    float acc[2][4][4];
#pragma unroll
    for (int mt = 0; mt < 2; mt++)
#pragma unroll
        for (int nt = 0; nt < 4; nt++)
#pragma unroll
            for (int e = 0; e < 4; e++) acc[mt][nt][e] = 0.f;

    issue(0);

    for (int i = 0; i < 16; ++i) {
        CP_WAIT0();
        __syncthreads();
        if (i + 1 < 16) issue(i + 1);
        const uint32_t base = smb + (i & 1) * STG3B2;
        const uint32_t AHB = base + (wn ? 2 * TILB2 : 0);
        const uint32_t ALB = AHB + TILB2;
        const uint32_t BHB = base + 4 * TILB2 + (wn ? 2 * BTB2 : 0);
        const uint32_t BLB = BHB + BTB2;
#pragma unroll
        for (int kh = 0; kh < 2; ++kh) {
            uint32_t ah[2][4], al[2][4];
#pragma unroll
            for (int mt = 0; mt < 2; mt++) {
                ldsm4(ah[mt], AHB + aoff + mt * 16 * PCHB + kh * 32);
                ldsm4(al[mt], ALB + aoff + mt * 16 * PCHB + kh * 32);
            }
#pragma unroll
            for (int nt = 0; nt < 4; nt++) {
                uint32_t bh[2], bl[2];
                ldsm2(bh, BHB + boff + nt * 8 * PCHB + kh * 32);
                ldsm2(bl, BLB + boff + nt * 8 * PCHB + kh * 32);
#pragma unroll
                for (int mt = 0; mt < 2; mt++) {
                    mma_bf16(acc[mt][nt], ah[mt], bh);
                    mma_bf16(acc[mt][nt], ah[mt], bl);
                    mma_bf16(acc[mt][nt], al[mt], bh);
                }
            }
        }
    }
    __syncthreads();

    float* Cs = (float*)smu;  // [128][66]
    {
        const float* bp = wn ? b2t : b2s;
#pragma unroll
        for (int mt = 0; mt < 2; mt++) {
            int r = wm * 32 + mt * 16 + (lane >> 2);
#pragma unroll
            for (int nt = 0; nt < 4; nt++) {
                int ccl = nt * 8 + ((lane & 3) << 1);
                int cg = wn * 32 + ccl;
                float bv0 = __ldg(bp + ccl), bv1 = __ldg(bp + ccl + 1);
                Cs[r * 66 + cg] = acc[mt][nt][0] + bv0;
                Cs[r * 66 + cg + 1] = acc[mt][nt][1] + bv1;
                Cs[(r + 8) * 66 + cg] = acc[mt][nt][2] + bv0;
                Cs[(r + 8) * 66 + cg + 1] = acc[mt][nt][3] + bv1;
            }
        }
    }
    __syncthreads();

    if (tid < 128) {
        int r = tid;
        size_t grow = row0 + r;
        const float* xr = X + grow * DD;
        float* xo = Xn + grow * DD;
        int x2off = dH - x1off;
        float ssum = 0.f;
#pragma unroll 8
        for (int j = 0; j < dH; j++) {
            float s = Cs[r * 66 + j];
            float t = Cs[r * 66 + 32 + j];
            float x1 = xr[x1off + j];
            float x2 = xr[x2off + j];
            float x1n = (x1 - mu[x1off + j]) * rstd[x1off + j];
            float x2n = (x2 - mu[x2off + j]) * rstd[x2off + j];
            float y2 = x2n * expf(s) + t;
            xo[j] = x1n;
            xo[dH + j] = y2;
            Cs[r * 66 + j] = x1n;
            Cs[r * 66 + 32 + j] = y2;
            ssum += s;
        }
        det[grow] = first ? ssum : (det[grow] + ssum);
    }
    __syncthreads();

    float* red = (float*)smu + 128 * 66;
    if (tid < 128) {
        int c = tid & 63;
        int half = tid >> 6;
        float s = 0.f, q = 0.f;
        int rbeg = half * 64;
#pragma unroll 4
        for (int r = rbeg; r < rbeg + 64; ++r) {
            float v = Cs[r * 66 + c];
            s += v;
            q += v * v;
        }
        red[tid] = s;
        red[128 + tid] = q;
    }
    __syncthreads();
    if (tid < 64) {
        part[blockIdx.x * 128 + tid] = red[tid] + red[64 + tid];
        part[blockIdx.x * 128 + 64 + tid] =
            red[128 + tid] + red[128 + 64 + tid];
    }
}

// ---------------------------------------------------------------------------
// GMM log-likelihood + output assembly + final reduce (unchanged, proven)
// ---------------------------------------------------------------------------
__global__ __launch_bounds__(256) void gmm_kernel(
    const float* __restrict__ X, const float* __restrict__ means,
    const float* __restrict__ det, float* __restrict__ out, int N, int full) {
    __shared__ float smm[KK * DD];
    int tid = threadIdx.x;
    for (int i = tid; i < KK * DD; i += 256) smm[i] = means[i];
    __syncthreads();

    size_t i = (size_t)blockIdx.x * 256 + tid;
    float4 y4[16];
    const float4* xr = (const float4*)(X + i * DD);
#pragma unroll
    for (int q = 0; q < 16; q++) y4[q] = xr[q];
    float4* yo = (float4*)(out + i * DD);
#pragma unroll
    for (int q = 0; q < 16; q++) yo[q] = y4[q];

    if (!full) return;

    const float CD = (float)(64.0 * 1.8378770664093453);
    float lp[KK];
    float mx = -1e30f;
#pragma unroll
    for (int k = 0; k < KK; k++) {
        const float* mrow = smm + k * DD;
        float accv = 0.f;
#pragma unroll
        for (int q = 0; q < 16; q++) {
            float4 m4 = *(const float4*)(mrow + q * 4);
            float dx = y4[q].x - m4.x;
            accv += dx * dx;
            dx = y4[q].y - m4.y;
            accv += dx * dx;
            dx = y4[q].z - m4.z;
            accv += dx * dx;
            dx = y4[q].w - m4.w;
            accv += dx * dx;
        }
        float v = -0.5f * (accv + CD);
        lp[k] = v;
        mx = fmaxf(mx, v);
    }
    float se = 0.f;
#pragma unroll
    for (int k = 0; k < KK; k++) se += expf(lp[k] - mx);
    float ll = mx + logf(se) - logf((float)KK);

    size_t oll = (size_t)N * DD + 1;
    out[oll + i] = ll;
    out[oll + N + i] = det[i];
}

__global__ void final_reduce_kernel(float* __restrict__ out, int N) {
    int tid = threadIdx.x;
    size_t oll = (size_t)N * DD + 1;
    size_t odet = oll + N;
    float sll = 0.f, sdet = 0.f;
    for (int i = tid; i < N; i += 1024) {
        sll += out[oll + i];
        sdet += out[odet + i];
    }
    __shared__ float a[1024], b[1024];
    a[tid] = sll;
    b[tid] = sdet;
    __syncthreads();
    for (int s = 512; s > 0; s >>= 1) {
        if (tid < s) {
            a[tid] += a[tid + s];
            b[tid] += b[tid + s];
        }
        __syncthreads();
    }
    if (tid == 0) {
        float llm = a[0] / (float)N;
        float dm = b[0] / (float)N;
        out[(size_t)N * DD] = -(dm + llm);
        out[odet + N] = llm;
        out[odet + N + 1] = dm;
    }
}

// ---------------------------------------------------------------------------
// Host launcher
// ---------------------------------------------------------------------------
static void* symaddr_v(const void* s) {
    void* p = nullptr;
    cudaGetSymbolAddress(&p, s);
    return p;
}

extern "C" void kernel_launch(void* const* d_in, const int* in_sizes, int n_in,
                              void* d_out, int out_size) {
    const float* x = (const float*)d_in[0];
    const float* sW0 = (const float*)d_in[1];
    const float* sb0 = (const float*)d_in[2];
    const float* sW1 = (const float*)d_in[3];
    const float* sb1 = (const float*)d_in[4];
    const float* sW2 = (const float*)d_in[5];
    const float* sb2 = (const float*)d_in[6];
    const float* tW0 = (const float*)d_in[7];
    const float* tb0 = (const float*)d_in[8];
    const float* tW1 = (const float*)d_in[9];
    const float* tb1 = (const float*)d_in[10];
    const float* tW2 = (const float*)d_in[11];
    const float* tb2 = (const float*)d_in[12];
    const float* means = (const float*)d_in[13];
    float* out = (float*)d_out;

    const int N = in_sizes[0] / (DD + 1);
    const int full = (out_size >= (long long)N * DD + 2 * N + 3) ? 1 : 0;

    cudaFuncSetAttribute(gemm2_kernel,
                         cudaFuncAttributeMaxDynamicSharedMemorySize, SMEMG2);
    cudaFuncSetAttribute(mma_gemm3_kernel,
                         cudaFuncAttributeMaxDynamicSharedMemorySize, SMEM3B);

    float* X = (float*)symaddr_v(g_X);
    float* det = (float*)symaddr_v(g_det);
    float* part = (float*)symaddr_v(g_part);
    float* mu = (float*)symaddr_v(g_mu);
    float* rstd = (float*)symaddr_v(g_rstd);
    unsigned short* Wh = (unsigned short*)symaddr_v(g_Wh);
    unsigned short* Wl = (unsigned short*)symaddr_v(g_Wl);
    unsigned short* H0h = (unsigned short*)symaddr_v(g_H0h);
    unsigned short* H0l = (unsigned short*)symaddr_v(g_H0l);
    unsigned short* H1h = (unsigned short*)symaddr_v(g_H1h);
    unsigned short* H1l = (unsigned short*)symaddr_v(g_H1l);

    const size_t XS = (size_t)N * DD;
    const size_t HS = (size_t)N * HH;

    copy_in_kernel<<<(N * DD + 255) / 256, 256>>>(x, X, N);

    wsplit_kernel<<<(65536 + 255) / 256, 256>>>(sW0, Wh + OFF_SW0,
                                                Wl + OFF_SW0, 65536);
    wsplit_kernel<<<(65536 + 255) / 256, 256>>>(tW0, Wh + OFF_TW0,
                                                Wl + OFF_TW0, 65536);
    wsplit_kernel<<<(1048576 + 255) / 256, 256>>>(sW1, Wh + OFF_SW1,
                                                  Wl + OFF_SW1, 1048576);
    wsplit_kernel<<<(1048576 + 255) / 256, 256>>>(tW1, Wh + OFF_TW1,
                                                  Wl + OFF_TW1, 1048576);
    wsplit_kernel<<<(65536 + 255) / 256, 256>>>(sW2, Wh + OFF_SW2,
                                                Wl + OFF_SW2, 65536);
    wsplit_kernel<<<(65536 + 255) / 256, 256>>>(tW2, Wh + OFF_TW2,
                                                Wl + OFF_TW2, 65536);

    int cur = 0;
    for (int l = 0; l < LL; l++) {
        float* Xc = X + (size_t)cur * XS;
        float* Xnext = X + (size_t)(cur ^ 1) * XS;

        if (l == 0) {
            stats1_kernel<<<256, 256>>>(Xc, part, N / 256);
            stats2_kernel<<<1, 64>>>(part, 256, 1.0f / (float)N, mu, rstd);
        } else {
            stats2_kernel<<<1, 64>>>(part, N / 128, 1.0f / (float)N, mu, rstd);
        }

        const int x1off = (l & 1) ? dH : 0;

        // GEMM1 with fused batchnorm-normalize on A (pitch-80 layout)
        gemm1_kernel<<<dim3(HH / 128, N / 128, 2), 256, SMEMG1>>>(
            Xc, x1off,
            Wh + OFF_SW0 + (size_t)l * HH * dH, Wl + OFF_SW0 + (size_t)l * HH * dH,
            Wh + OFF_TW0 + (size_t)l * HH * dH, Wl + OFF_TW0 + (size_t)l * HH * dH,
            sb0 + (size_t)l * HH, tb0 + (size_t)l * HH,
            H0h, H0l, H0h + HS, H0l + HS, mu, rstd);

        gemm2_kernel<<<dim3(HH / 128, N / 128, 2), 256, SMEMG2>>>(
            H0h, H0l, H0h + HS, H0l + HS,
            Wh + OFF_SW1 + (size_t)l * HH * HH, Wl + OFF_SW1 + (size_t)l * HH * HH,
            Wh + OFF_TW1 + (size_t)l * HH * HH, Wl + OFF_TW1 + (size_t)l * HH * HH,
            sb1 + (size_t)l * HH, tb1 + (size_t)l * HH,
            H1h, H1l, H1h + HS, H1l + HS);

        mma_gemm3_kernel<<<N / 128, 256, SMEM3B>>>(
            H1h, H1l, H1h + HS, H1l + HS,
            Wh + OFF_SW2 + (size_t)l * dH * HH, Wl + OFF_SW2 + (size_t)l * dH * HH,
            Wh + OFF_TW2 + (size_t)l * dH * HH, Wl + OFF_TW2 + (size_t)l * dH * HH,
            sb2 + (size_t)l * dH, tb2 + (size_t)l * dH, Xc, Xnext, mu, rstd,
            det, part, x1off, (l == 0) ? 1 : 0);

        cur ^= 1;
    }

    gmm_kernel<<<N / 256, 256>>>(X + (size_t)cur * XS, means, det, out, N,
                                 full);
    if (full) final_reduce_kernel<<<1, 1024>>>(out, N);
}